// round 1
// baseline (speedup 1.0000x reference)
#include <cuda_runtime.h>
#include <cstdint>

// Problem constants
#define B_ROWS   1024
#define NL       64
#define NH       32
#define NG       20000
#define NC       64
#define GOI      1000
#define LOGIT_N  (GOI * NC)       // 64000
#define EPSV     1e-5f

// Scratch (static device arrays only — no allocation allowed)
__device__ float g_h[B_ROWS * NH];   // h, pre-rounded to tf32 bit patterns
__device__ int   g_genes[GOI];       // normalized gene indices

__device__ __forceinline__ uint32_t tf32r(float x) {
    uint32_t u;
    asm("cvt.rna.tf32.f32 %0, %1;" : "=r"(u) : "f"(x));
    return u;
}

__device__ __forceinline__ void mma_tf32(float (&c)[4],
                                         uint32_t a0, uint32_t a1, uint32_t a2, uint32_t a3,
                                         uint32_t b0, uint32_t b1) {
    asm volatile(
        "mma.sync.aligned.m16n8k8.row.col.f32.tf32.tf32.f32 "
        "{%0,%1,%2,%3}, {%4,%5,%6,%7}, {%8,%9}, {%0,%1,%2,%3};"
        : "+f"(c[0]), "+f"(c[1]), "+f"(c[2]), "+f"(c[3])
        : "r"(a0), "r"(a1), "r"(a2), "r"(a3), "r"(b0), "r"(b1));
}

// ---------------------------------------------------------------------------
// Prep: genes_oi may be int64 (jnp.int64) or int32 (JAX without x64 silently
// downcasts). Detect via high-word-zero pattern and normalize to int32.
// ---------------------------------------------------------------------------
__global__ void prep_genes(const void* __restrict__ genes_raw) {
    __shared__ int odd_zero_cnt;
    if (threadIdx.x == 0) odd_zero_cnt = 0;
    __syncthreads();

    const int* p32 = (const int*)genes_raw;
    int local = 0;
    for (int i = threadIdx.x; i < GOI; i += blockDim.x)
        if ((i & 1) && p32[i] == 0) local++;
    if (local) atomicAdd(&odd_zero_cnt, local);
    __syncthreads();

    bool is64 = (odd_zero_cnt >= 100);   // int64 => ~500 zero high-words in first 1000 words
    const long long* p64 = (const long long*)genes_raw;
    for (int i = threadIdx.x; i < GOI; i += blockDim.x) {
        long long v = is64 ? p64[i] : (long long)p32[i];
        if (v < 0) v = 0;
        if (v > NG - 1) v = NG - 1;
        g_genes[i] = (int)v;
    }
}

// ---------------------------------------------------------------------------
// Stage 1: h = relu( (latent@W + b - mean) * rsqrt(var+eps) * gamma + beta )
// 128 blocks x 256 threads; each block: 8 batch rows x 32 hidden units.
// Output pre-rounded to tf32 (round-to-nearest) so the GEMM A-operand is clean.
// ---------------------------------------------------------------------------
__global__ void compute_h(const float* __restrict__ latent,
                          const float* __restrict__ W,
                          const float* __restrict__ bias,
                          const float* __restrict__ gamma,
                          const float* __restrict__ beta,
                          const float* __restrict__ mean,
                          const float* __restrict__ var) {
    __shared__ float lat_s[8][64];
    __shared__ float w_s[64][32];

    int tid = threadIdx.x;
    for (int i = tid; i < NL * NH; i += 256)
        w_s[i >> 5][i & 31] = W[i];

    int b0 = blockIdx.x * 8;
    for (int i = tid; i < 8 * NL; i += 256)
        lat_s[i >> 6][i & 63] = latent[(size_t)b0 * NL + i];
    __syncthreads();

    int br = tid >> 5;
    int j  = tid & 31;

    float s  = rsqrtf(var[j] + EPSV) * gamma[j];
    float sh = fmaf(-mean[j], s, beta[j]);
    sh = fmaf(bias[j], s, sh);

    float acc = 0.f;
#pragma unroll
    for (int l = 0; l < NL; l++)
        acc = fmaf(lat_s[br][l], w_s[l][j], acc);

    float h = fmaxf(0.f, fmaf(acc, s, sh));
    g_h[(b0 + br) * NH + j] = __uint_as_float(tf32r(h));
}

// ---------------------------------------------------------------------------
// Tiled GEMM: C[m, col0+n] = sum_k h[m,k] * Bmat[k,n],  K = 32 (unrolled).
// CTA: 256 threads (8 warps), tile M=256, N=64.
//   mode 0 (logit): B source = logit_table[g_genes[blockIdx.x]] as [K=32][N=64]
//   mode 1 (rho):   B source = rho_table rows [n][k], n = col0..col0+63
// smem staged transposed as b_s[n][k] with row stride 36 -> conflict-free
// fragment loads; h_s row stride 36 likewise.
// ---------------------------------------------------------------------------
__global__ __launch_bounds__(256) void gemm_tile(const float* __restrict__ table,
                                                 float* __restrict__ out,
                                                 int ncols, int ld, int mode) {
    __shared__ float h_s[256 * 36];
    __shared__ float b_s[64 * 36];

    int tid  = threadIdx.x;
    int m0   = blockIdx.y * 256;
    int col0 = blockIdx.x * 64;

    // Stage h tile (256 x 32)
#pragma unroll 4
    for (int i = tid; i < 256 * NH; i += 256) {
        int r = i >> 5, c = i & 31;
        h_s[r * 36 + c] = g_h[(m0 + r) * NH + c];
    }

    // Stage B tile transposed to [n][k], tf32-rounded
    if (mode == 0) {
        const float* src = table + (size_t)g_genes[blockIdx.x] * (NH * NC);
#pragma unroll 4
        for (int i = tid; i < NH * NC; i += 256) {
            int k = i >> 6, n = i & 63;
            b_s[n * 36 + k] = __uint_as_float(tf32r(src[i]));
        }
    } else {
        const float* src = table + (size_t)col0 * NH;
#pragma unroll 4
        for (int i = tid; i < NH * NC; i += 256) {
            int n = i >> 5, k = i & 31;
            float v = (col0 + n < ncols) ? src[i] : 0.f;
            b_s[n * 36 + k] = __uint_as_float(tf32r(v));
        }
    }
    __syncthreads();

    int warp = tid >> 5, lane = tid & 31;
    int g = lane >> 2, tg = lane & 3;
    int mbase = warp * 32;

    float acc[2][8][4];
#pragma unroll
    for (int mf = 0; mf < 2; mf++)
#pragma unroll
        for (int nf = 0; nf < 8; nf++)
#pragma unroll
            for (int q = 0; q < 4; q++)
                acc[mf][nf][q] = 0.f;

    const uint32_t* hu = (const uint32_t*)h_s;
    const uint32_t* bu = (const uint32_t*)b_s;

#pragma unroll
    for (int kk = 0; kk < 4; kk++) {
        uint32_t a[2][4];
#pragma unroll
        for (int mf = 0; mf < 2; mf++) {
            int r = mbase + mf * 16 + g;
            int c = kk * 8 + tg;
            a[mf][0] = hu[r * 36 + c];
            a[mf][1] = hu[(r + 8) * 36 + c];
            a[mf][2] = hu[r * 36 + c + 4];
            a[mf][3] = hu[(r + 8) * 36 + c + 4];
        }
#pragma unroll
        for (int nf = 0; nf < 8; nf++) {
            uint32_t b0v = bu[(nf * 8 + g) * 36 + kk * 8 + tg];
            uint32_t b1v = bu[(nf * 8 + g) * 36 + kk * 8 + tg + 4];
            mma_tf32(acc[0][nf], a[0][0], a[0][1], a[0][2], a[0][3], b0v, b1v);
            mma_tf32(acc[1][nf], a[1][0], a[1][1], a[1][2], a[1][3], b0v, b1v);
        }
    }

    // Epilogue: each 4-lane group writes one full 32B sector per row per nf.
#pragma unroll
    for (int mf = 0; mf < 2; mf++) {
        int r0 = m0 + mbase + mf * 16 + g;
#pragma unroll
        for (int nf = 0; nf < 8; nf++) {
            int c = col0 + nf * 8 + 2 * tg;
            if (c < ncols) {
                float2 v0 = make_float2(acc[mf][nf][0], acc[mf][nf][1]);
                float2 v1 = make_float2(acc[mf][nf][2], acc[mf][nf][3]);
                *(float2*)(out + (size_t)r0 * ld + c)       = v0;
                *(float2*)(out + (size_t)(r0 + 8) * ld + c) = v1;
            }
        }
    }
}

// ---------------------------------------------------------------------------
// Launch
// in order: latent, genes_oi, W, b, bn_gamma, bn_beta, bn_mean, bn_var,
//           logit_table, rho_table
// out: [logit (1024*1000*64) | rho (1024*20000)] fp32
// ---------------------------------------------------------------------------
extern "C" void kernel_launch(void* const* d_in, const int* in_sizes, int n_in,
                              void* d_out, int out_size) {
    const float* latent      = (const float*)d_in[0];
    const void*  genes_raw   = d_in[1];
    const float* W           = (const float*)d_in[2];
    const float* bias        = (const float*)d_in[3];
    const float* bn_gamma    = (const float*)d_in[4];
    const float* bn_beta     = (const float*)d_in[5];
    const float* bn_mean     = (const float*)d_in[6];
    const float* bn_var      = (const float*)d_in[7];
    const float* logit_table = (const float*)d_in[8];
    const float* rho_table   = (const float*)d_in[9];

    float* out_logit = (float*)d_out;
    float* out_rho   = out_logit + (size_t)B_ROWS * LOGIT_N;

    prep_genes<<<1, 256>>>(genes_raw);
    compute_h<<<B_ROWS / 8, 256>>>(latent, W, bias, bn_gamma, bn_beta, bn_mean, bn_var);

    // logit: 1000 genes x 4 batch tiles
    gemm_tile<<<dim3(GOI, B_ROWS / 256), 256>>>(logit_table, out_logit, LOGIT_N, LOGIT_N, 0);
    // rho: ceil(20000/64)=313 col tiles x 4 batch tiles
    gemm_tile<<<dim3((NG + 63) / 64, B_ROWS / 256), 256>>>(rho_table, out_rho, NG, NG, 1);
}

// round 2
// speedup vs baseline: 1.7167x; 1.7167x over previous
#include <cuda_runtime.h>
#include <cstdint>

// Problem constants
#define B_ROWS   1024
#define NL       64
#define NH       32
#define NG       20000
#define NC       64
#define GOI      1000
#define LOGIT_N  (GOI * NC)       // 64000
#define EPSV     1e-5f

#define MTILES   (B_ROWS / 128)   // 8
#define LOGIT_BLKS (GOI * MTILES) // 8000
#define RHO_CTILES ((NG + 63) / 64) // 313
#define RHO_BLKS (RHO_CTILES * MTILES) // 2504

// Scratch (static device arrays only — no allocation allowed)
__device__ float g_h[B_ROWS * NH];   // h, pre-rounded to tf32 bit patterns
__device__ int   g_genes[GOI];       // normalized gene indices

__device__ __forceinline__ uint32_t tf32r(float x) {
    uint32_t u;
    asm("cvt.rna.tf32.f32 %0, %1;" : "=r"(u) : "f"(x));
    return u;
}

__device__ __forceinline__ void mma_tf32(float (&c)[4],
                                         uint32_t a0, uint32_t a1, uint32_t a2, uint32_t a3,
                                         uint32_t b0, uint32_t b1) {
    asm volatile(
        "mma.sync.aligned.m16n8k8.row.col.f32.tf32.tf32.f32 "
        "{%0,%1,%2,%3}, {%4,%5,%6,%7}, {%8,%9}, {%0,%1,%2,%3};"
        : "+f"(c[0]), "+f"(c[1]), "+f"(c[2]), "+f"(c[3])
        : "r"(a0), "r"(a1), "r"(a2), "r"(a3), "r"(b0), "r"(b1));
}

__device__ __forceinline__ uint32_t smem_u32(const void* p) {
    uint32_t a;
    asm("{ .reg .u64 t; cvta.to.shared.u64 t, %1; cvt.u32.u64 %0, t; }"
        : "=r"(a) : "l"(p));
    return a;
}

__device__ __forceinline__ void cp_async16(uint32_t dst, const void* src) {
    asm volatile("cp.async.ca.shared.global [%0], [%1], 16;" :: "r"(dst), "l"(src));
}

// Column permutation: real output col n -> fragment col index n'
// real n = 16P + 4t + 2f + j  ==>  frag n' = 16P + 8f + 2t + j
// so a thread's two paired n-fragments hold 4 consecutive real columns.
__device__ __forceinline__ int permc(int n) {
    return (n & 0x30) | ((n & 0x02) << 2) | ((n & 0x0C) >> 1) | (n & 1);
}

// ---------------------------------------------------------------------------
// Stage 1 (fused): blocks 0..127 compute h rows; last block normalizes genes.
// h = relu( (latent@W + b - mean) * rsqrt(var+eps) * gamma + beta ), tf32-rounded
// ---------------------------------------------------------------------------
__global__ void compute_h(const float* __restrict__ latent,
                          const float* __restrict__ W,
                          const float* __restrict__ bias,
                          const float* __restrict__ gamma,
                          const float* __restrict__ beta,
                          const float* __restrict__ mean,
                          const float* __restrict__ var,
                          const void*  __restrict__ genes_raw) {
    if (blockIdx.x == gridDim.x - 1) {
        // gene index normalization: int64 vs int32 detection
        __shared__ int odd_zero_cnt;
        if (threadIdx.x == 0) odd_zero_cnt = 0;
        __syncthreads();
        const int* p32 = (const int*)genes_raw;
        int local = 0;
        for (int i = threadIdx.x; i < GOI; i += blockDim.x)
            if ((i & 1) && p32[i] == 0) local++;
        if (local) atomicAdd(&odd_zero_cnt, local);
        __syncthreads();
        bool is64 = (odd_zero_cnt >= 100);
        const long long* p64 = (const long long*)genes_raw;
        for (int i = threadIdx.x; i < GOI; i += blockDim.x) {
            long long v = is64 ? p64[i] : (long long)p32[i];
            if (v < 0) v = 0;
            if (v > NG - 1) v = NG - 1;
            g_genes[i] = (int)v;
        }
        return;
    }

    __shared__ float lat_s[8][64];
    __shared__ float w_s[64][32];

    int tid = threadIdx.x;
    for (int i = tid; i < NL * NH; i += 256)
        w_s[i >> 5][i & 31] = W[i];

    int b0 = blockIdx.x * 8;
    for (int i = tid; i < 8 * NL; i += 256)
        lat_s[i >> 6][i & 63] = latent[(size_t)b0 * NL + i];
    __syncthreads();

    int br = tid >> 5;
    int j  = tid & 31;

    float s  = rsqrtf(var[j] + EPSV) * gamma[j];
    float sh = fmaf(-mean[j], s, beta[j]);
    sh = fmaf(bias[j], s, sh);

    float acc = 0.f;
#pragma unroll
    for (int l = 0; l < NL; l++)
        acc = fmaf(lat_s[br][l], w_s[l][j], acc);

    float h = fmaxf(0.f, fmaf(acc, s, sh));
    g_h[(b0 + br) * NH + j] = __uint_as_float(tf32r(h));
}

// ---------------------------------------------------------------------------
// Fused GEMM: one grid covers both outputs.
//   blocks [0, 8000):      logit  — gene = bx>>3, mtile = bx&7
//   blocks [8000, 10504):   rho   — ctile = (bx-8000)>>3, mtile = (bx-8000)&7
// CTA: 256 threads = 8 warps (4 in M x 2 in N). CTA tile M=128, N=64, K=32.
// Warp tile 32x32 via tf32 m16n8k8, acc = 32 regs/thread.
// B staged transposed+column-permuted so epilogue is pure STG.128 (.cs).
// ---------------------------------------------------------------------------
__global__ __launch_bounds__(256, 4) void gemm_fused(
        const float* __restrict__ logit_table,
        const float* __restrict__ rho_table,
        float* __restrict__ out_logit,
        float* __restrict__ out_rho) {
    __shared__ float h_s[128 * 36];
    __shared__ float b_s[64 * 36];

    int tid = threadIdx.x;
    int bx  = blockIdx.x;

    bool is_logit = bx < LOGIT_BLKS;
    int m0, col0, ld, ncols;
    float* out;
    const float* bsrc;

    if (is_logit) {
        int gene = bx >> 3;
        m0    = (bx & 7) * 128;
        col0  = gene * NC;
        ld    = LOGIT_N;
        ncols = LOGIT_N;
        out   = out_logit;
        bsrc  = logit_table + (size_t)g_genes[gene] * (NH * NC);
    } else {
        int bxr = bx - LOGIT_BLKS;
        int ct  = bxr >> 3;
        m0    = (bxr & 7) * 128;
        col0  = ct * 64;
        ld    = NG;
        ncols = NG;
        out   = out_rho;
        bsrc  = rho_table + (size_t)col0 * NH;
    }

    // --- Stage h tile (128 x 32) via cp.async; g_h already tf32-rounded ---
    uint32_t hs_base = smem_u32(h_s);
#pragma unroll
    for (int it = 0; it < 4; it++) {
        int q   = tid + it * 256;      // 16B-chunk index (1024 total)
        int row = q >> 3, seg = q & 7;
        cp_async16(hs_base + (uint32_t)(row * 36 + seg * 4) * 4,
                   g_h + (m0 + row) * NH + seg * 4);
    }
    asm volatile("cp.async.commit_group;");

    // --- Stage B tile transposed + permuted into b_s[n'][k] ---
    if (is_logit) {
        // src layout [k=32][n=64] row-major
#pragma unroll
        for (int it = 0; it < 2; it++) {
            int q  = tid + it * 256;           // float4 index (512 total)
            int k  = q >> 4;                   // 16 float4 per k-row
            int n4 = (q & 15) * 4;
            float4 v = __ldg((const float4*)bsrc + q);
            b_s[permc(n4 + 0) * 36 + k] = __uint_as_float(tf32r(v.x));
            b_s[permc(n4 + 1) * 36 + k] = __uint_as_float(tf32r(v.y));
            b_s[permc(n4 + 2) * 36 + k] = __uint_as_float(tf32r(v.z));
            b_s[permc(n4 + 3) * 36 + k] = __uint_as_float(tf32r(v.w));
        }
    } else {
        // src layout [n][k=32] row-major (rho_table rows)
#pragma unroll
        for (int it = 0; it < 2; it++) {
            int q  = tid + it * 256;           // float4 index (512 total)
            int n  = q >> 3;                   // 8 float4 per n-row
            int k4 = (q & 7) * 4;
            float4 v = make_float4(0.f, 0.f, 0.f, 0.f);
            if (col0 + n < ncols)
                v = __ldg((const float4*)(bsrc + (size_t)n * NH + k4));
            int np = permc(n) * 36;
            b_s[np + k4 + 0] = __uint_as_float(tf32r(v.x));
            b_s[np + k4 + 1] = __uint_as_float(tf32r(v.y));
            b_s[np + k4 + 2] = __uint_as_float(tf32r(v.z));
            b_s[np + k4 + 3] = __uint_as_float(tf32r(v.w));
        }
    }

    asm volatile("cp.async.wait_group 0;");
    __syncthreads();

    // --- Compute: warp (wm, wn) covers rows wm*32..+31, frag cols wn*32..+31 ---
    int warp = tid >> 5, lane = tid & 31;
    int g  = lane >> 2, tg = lane & 3;
    int wm = warp >> 1, wn = warp & 1;
    int mb = wm * 32;
    int nb = wn * 32;

    float acc[2][2][2][4];   // [mf][pair][frag][4]
#pragma unroll
    for (int a = 0; a < 2; a++)
#pragma unroll
        for (int b = 0; b < 2; b++)
#pragma unroll
            for (int c = 0; c < 2; c++)
#pragma unroll
                for (int d = 0; d < 4; d++)
                    acc[a][b][c][d] = 0.f;

    const uint32_t* hu = (const uint32_t*)h_s;
    const uint32_t* bu = (const uint32_t*)b_s;

#pragma unroll
    for (int kk = 0; kk < 4; kk++) {
        uint32_t a[2][4];
#pragma unroll
        for (int mf = 0; mf < 2; mf++) {
            int r = mb + mf * 16 + g;
            int c = kk * 8 + tg;
            a[mf][0] = hu[r * 36 + c];
            a[mf][1] = hu[(r + 8) * 36 + c];
            a[mf][2] = hu[r * 36 + c + 4];
            a[mf][3] = hu[(r + 8) * 36 + c + 4];
        }
#pragma unroll
        for (int p = 0; p < 2; p++)
#pragma unroll
            for (int f = 0; f < 2; f++) {
                int nrow = nb + p * 16 + f * 8 + g;
                uint32_t b0v = bu[nrow * 36 + kk * 8 + tg];
                uint32_t b1v = bu[nrow * 36 + kk * 8 + tg + 4];
                mma_tf32(acc[0][p][f], a[0][0], a[0][1], a[0][2], a[0][3], b0v, b1v);
                mma_tf32(acc[1][p][f], a[1][0], a[1][1], a[1][2], a[1][3], b0v, b1v);
            }
    }

    // --- Epilogue: pure STG.128 streaming stores, 4 consecutive cols/thread ---
#pragma unroll
    for (int mf = 0; mf < 2; mf++) {
#pragma unroll
        for (int p = 0; p < 2; p++) {
            int row = m0 + mb + mf * 16 + g;
            int col = col0 + nb + p * 16 + 4 * tg;
            if (col < ncols) {
                float4 v0 = make_float4(acc[mf][p][0][0], acc[mf][p][0][1],
                                        acc[mf][p][1][0], acc[mf][p][1][1]);
                float4 v1 = make_float4(acc[mf][p][0][2], acc[mf][p][0][3],
                                        acc[mf][p][1][2], acc[mf][p][1][3]);
                __stcs((float4*)(out + (size_t)row * ld + col), v0);
                __stcs((float4*)(out + (size_t)(row + 8) * ld + col), v1);
            }
        }
    }
}

// ---------------------------------------------------------------------------
// Launch
// ---------------------------------------------------------------------------
extern "C" void kernel_launch(void* const* d_in, const int* in_sizes, int n_in,
                              void* d_out, int out_size) {
    const float* latent      = (const float*)d_in[0];
    const void*  genes_raw   = d_in[1];
    const float* W           = (const float*)d_in[2];
    const float* bias        = (const float*)d_in[3];
    const float* bn_gamma    = (const float*)d_in[4];
    const float* bn_beta     = (const float*)d_in[5];
    const float* bn_mean     = (const float*)d_in[6];
    const float* bn_var      = (const float*)d_in[7];
    const float* logit_table = (const float*)d_in[8];
    const float* rho_table   = (const float*)d_in[9];

    float* out_logit = (float*)d_out;
    float* out_rho   = out_logit + (size_t)B_ROWS * LOGIT_N;

    compute_h<<<B_ROWS / 8 + 1, 256>>>(latent, W, bias, bn_gamma, bn_beta,
                                       bn_mean, bn_var, genes_raw);
    gemm_fused<<<LOGIT_BLKS + RHO_BLKS, 256>>>(logit_table, rho_table,
                                               out_logit, out_rho);
}